// round 3
// baseline (speedup 1.0000x reference)
#include <cuda_runtime.h>
#include <stdint.h>

// Batched upper-triangular scatter:
//   out[b, r, c] = in[b, r*M - r*(r-1)/2 + (c-r)]  if c >= r, else 0
// M = 1024, TRIU = 524800, B = 128.
//
// Pure bandwidth kernel: 256 MiB read + 512 MiB write (both mandatory).
// R2: 8 rows per block -> 8 independent float4 loads front-batched (MLP=8),
// then 8 streaming float4 stores. Zero rows skip the read path entirely.

#define MAT_M 1024
#define TRIU_LEN 524800
#define ROWS_PER_BLK 8

__device__ __forceinline__ float4 ldcs4(const float* p) {
    float4 v;
    v.x = __ldcs(p + 0);
    v.y = __ldcs(p + 1);
    v.z = __ldcs(p + 2);
    v.w = __ldcs(p + 3);
    return v;
}

__global__ void __launch_bounds__(256, 6)
triu_scatter_kernel(const float* __restrict__ in, float* __restrict__ out)
{
    const int r0 = blockIdx.x * ROWS_PER_BLK;   // 0,8,...,1016
    const int b  = blockIdx.y;                  // 0..B-1
    const int c0 = threadIdx.x << 2;            // 0,4,...,1020

    const float* __restrict__ inb = in + (size_t)b * TRIU_LEN;

    float4 v[ROWS_PER_BLK];

    // ---- Phase 1: batch all loads (independent -> deep MLP) ----
    #pragma unroll
    for (int j = 0; j < ROWS_PER_BLK; ++j) {
        const int r = r0 + j;
        // rowstart = r*M - r*(r-1)/2, max 524799 (fits int)
        const int rowstart = r * MAT_M - ((r * (r - 1)) >> 1);

        if (c0 >= r) {
            // Fully inside upper triangle: contiguous packed load.
            v[j] = ldcs4(inb + rowstart + (c0 - r));
        } else if (c0 + 3 < r) {
            // Fully below diagonal: pure zero store, no read.
            v[j] = make_float4(0.f, 0.f, 0.f, 0.f);
        } else {
            // Straddles the diagonal (<=1 thread per row).
            float t[4];
            #pragma unroll
            for (int k = 0; k < 4; ++k) {
                const int c = c0 + k;
                t[k] = (c >= r) ? __ldcs(inb + rowstart + (c - r)) : 0.f;
            }
            v[j] = make_float4(t[0], t[1], t[2], t[3]);
        }
    }

    // ---- Phase 2: aligned streaming float4 stores ----
    const size_t base = (((size_t)b * MAT_M + (size_t)r0) * MAT_M) + (size_t)c0;
    #pragma unroll
    for (int j = 0; j < ROWS_PER_BLK; ++j) {
        __stcs(reinterpret_cast<float4*>(out + base + (size_t)j * MAT_M), v[j]);
    }
}

extern "C" void kernel_launch(void* const* d_in, const int* in_sizes, int n_in,
                              void* d_out, int out_size)
{
    const float* in = (const float*)d_in[0];
    float* out = (float*)d_out;

    const int B = in_sizes[0] / TRIU_LEN;   // 128 for the bench shape

    dim3 grid(MAT_M / ROWS_PER_BLK, B);
    dim3 block(256);
    triu_scatter_kernel<<<grid, block>>>(in, out);
}